// round 1
// baseline (speedup 1.0000x reference)
#include <cuda_runtime.h>

#define NN 50000
#define NE 600000
#define C  128
#define TM 64

// ---------------- scratch (static __device__, no runtime alloc) ----------------
__device__ float g_dis[NN];
__device__ float g_t[NN * C];     // GEMM output (pre-aggregation features)
__device__ float g_skip[NN * C];  // skip connection, then reused as u
__device__ float g_agg[NN * C];   // aggregation accumulator

// ---------------- f32x2 packed-FMA helpers (sm_100) ----------------
__device__ __forceinline__ unsigned long long bcast2(float v) {
    unsigned long long r;
    asm("mov.b64 %0, {%1, %1};" : "=l"(r) : "f"(v));
    return r;
}
__device__ __forceinline__ void fma2(unsigned long long& d, unsigned long long a,
                                     unsigned long long b) {
    asm("fma.rn.f32x2 %0, %1, %2, %0;" : "+l"(d) : "l"(a), "l"(b));
}
__device__ __forceinline__ float2 unpk2(unsigned long long v) {
    float2 f;
    asm("mov.b64 {%0, %1}, %2;" : "=f"(f.x), "=f"(f.y) : "l"(v));
    return f;
}

// ---------------- degree / norm ----------------
__global__ void k_deg_init(float* deg) {
    int i = blockIdx.x * blockDim.x + threadIdx.x;
    if (i < NN) deg[i] = 1.0f;  // self loop
}
__global__ void k_deg_count(const int* __restrict__ dst, float* deg) {
    int e = blockIdx.x * blockDim.x + threadIdx.x;
    if (e < NE) atomicAdd(&deg[dst[e]], 1.0f);
}
__global__ void k_dis(float* deg) {
    int i = blockIdx.x * blockDim.x + threadIdx.x;
    if (i < NN) deg[i] = rsqrtf(deg[i]);  // deg >= 1 always (self loops)
}

// ---------------- dual GEMM: t = x@W0 ; skip = x@Ws + bs ----------------
// block = 256 threads, TM=64 rows. smem: W0(64K) + Ws(64K) + xtile(32K) = 160K.
__global__ __launch_bounds__(256) void k_gemm_dual(
    const float* __restrict__ x, const float* __restrict__ W0,
    const float* __restrict__ Ws, const float* __restrict__ bs,
    float* __restrict__ t, float* __restrict__ skip) {
    extern __shared__ float sm[];
    float* w0s = sm;              // [C][C]
    float* wss = sm + C * C;      // [C][C]
    float* xs  = sm + 2 * C * C;  // [TM][C]

    int tid = threadIdx.x;
    for (int i = tid; i < C * C / 4; i += 256) {
        ((float4*)w0s)[i] = ((const float4*)W0)[i];
        ((float4*)wss)[i] = ((const float4*)Ws)[i];
    }
    int row0 = blockIdx.x * TM;
    for (int i = tid; i < TM * C / 4; i += 256) {
        int r = i / (C / 4);
        int gr = row0 + r;
        ((float4*)xs)[i] = (gr < NN) ? ((const float4*)x)[gr * (C / 4) + (i % (C / 4))]
                                     : make_float4(0.f, 0.f, 0.f, 0.f);
    }
    __syncthreads();

    int warp = tid >> 5, lane = tid & 31;
    int r0 = warp * 8;        // 8 warps x 8 rows = 64 rows
    int c0 = lane * 4;        // 32 lanes x 4 cols = 128 cols

    unsigned long long acc0[8][2], accs[8][2];
#pragma unroll
    for (int i = 0; i < 8; i++) {
        acc0[i][0] = acc0[i][1] = 0ull;
        accs[i][0] = accs[i][1] = 0ull;
    }

    for (int k = 0; k < C; k++) {
        ulonglong2 w0 = *(ulonglong2*)&w0s[k * C + c0];
        ulonglong2 wsv = *(ulonglong2*)&wss[k * C + c0];
#pragma unroll
        for (int i = 0; i < 8; i++) {
            unsigned long long xv = bcast2(xs[(r0 + i) * C + k]);
            fma2(acc0[i][0], xv, w0.x);
            fma2(acc0[i][1], xv, w0.y);
            fma2(accs[i][0], xv, wsv.x);
            fma2(accs[i][1], xv, wsv.y);
        }
    }

    float4 bsv = *(const float4*)&bs[c0];
#pragma unroll
    for (int i = 0; i < 8; i++) {
        int gr = row0 + r0 + i;
        if (gr < NN) {
            float2 a = unpk2(acc0[i][0]), b = unpk2(acc0[i][1]);
            *(float4*)&t[gr * C + c0] = make_float4(a.x, a.y, b.x, b.y);
            float2 sa = unpk2(accs[i][0]), sb = unpk2(accs[i][1]);
            *(float4*)&skip[gr * C + c0] =
                make_float4(sa.x + bsv.x, sa.y + bsv.y, sb.x + bsv.z, sb.y + bsv.w);
        }
    }
}

// ---------------- single GEMM: t = u@W1 ----------------
__global__ __launch_bounds__(256) void k_gemm_single(
    const float* __restrict__ u, const float* __restrict__ W1, float* __restrict__ t) {
    extern __shared__ float sm[];
    float* w1s = sm;          // [C][C]
    float* xs  = sm + C * C;  // [TM][C]

    int tid = threadIdx.x;
    for (int i = tid; i < C * C / 4; i += 256)
        ((float4*)w1s)[i] = ((const float4*)W1)[i];
    int row0 = blockIdx.x * TM;
    for (int i = tid; i < TM * C / 4; i += 256) {
        int r = i / (C / 4);
        int gr = row0 + r;
        ((float4*)xs)[i] = (gr < NN) ? ((const float4*)u)[gr * (C / 4) + (i % (C / 4))]
                                     : make_float4(0.f, 0.f, 0.f, 0.f);
    }
    __syncthreads();

    int warp = tid >> 5, lane = tid & 31;
    int r0 = warp * 8;
    int c0 = lane * 4;

    unsigned long long acc[8][2];
#pragma unroll
    for (int i = 0; i < 8; i++) acc[i][0] = acc[i][1] = 0ull;

    for (int k = 0; k < C; k++) {
        ulonglong2 w = *(ulonglong2*)&w1s[k * C + c0];
#pragma unroll
        for (int i = 0; i < 8; i++) {
            unsigned long long xv = bcast2(xs[(r0 + i) * C + k]);
            fma2(acc[i][0], xv, w.x);
            fma2(acc[i][1], xv, w.y);
        }
    }
#pragma unroll
    for (int i = 0; i < 8; i++) {
        int gr = row0 + r0 + i;
        if (gr < NN) {
            float2 a = unpk2(acc[i][0]), b = unpk2(acc[i][1]);
            *(float4*)&t[gr * C + c0] = make_float4(a.x, a.y, b.x, b.y);
        }
    }
}

// ---------------- agg init: agg = b + t * dis^2 (bias + self loop) ----------------
__global__ void k_agg_init(const float* __restrict__ t, const float* __restrict__ b,
                           const float* __restrict__ dis, float* __restrict__ agg) {
    int idx = blockIdx.x * blockDim.x + threadIdx.x;  // over NN*32 float4s
    if (idx >= NN * 32) return;
    int i = idx >> 5, c4 = idx & 31;
    float d = dis[i];
    float d2 = d * d;
    float4 tv = ((const float4*)t)[idx];
    float4 bv = ((const float4*)b)[c4];
    ((float4*)agg)[idx] = make_float4(bv.x + tv.x * d2, bv.y + tv.y * d2,
                                      bv.z + tv.z * d2, bv.w + tv.w * d2);
}

// ---------------- edge scatter: one warp per edge, float4 vector atomics ----------------
__global__ void k_scatter(const int* __restrict__ src, const int* __restrict__ dst,
                          const float* __restrict__ dis, const float* __restrict__ t,
                          float* __restrict__ agg) {
    int gw = (blockIdx.x * blockDim.x + threadIdx.x) >> 5;
    int lane = threadIdx.x & 31;
    if (gw >= NE) return;
    int s = src[gw], d = dst[gw];
    float w = dis[s] * dis[d];
    float4 v = ((const float4*)t)[s * 32 + lane];
    v.x *= w; v.y *= w; v.z *= w; v.w *= w;
    atomicAdd(((float4*)agg) + d * 32 + lane, v);
}

// ---------------- u = skip + prelu(agg, a)  (in place over skip) ----------------
__global__ void k_prelu_add(const float* __restrict__ agg, const float* __restrict__ a,
                            float* __restrict__ skip) {
    int idx = blockIdx.x * blockDim.x + threadIdx.x;
    if (idx >= NN * 32) return;
    int c4 = idx & 31;
    float4 av = ((const float4*)a)[c4];
    float4 g = ((const float4*)agg)[idx];
    g.x = g.x >= 0.f ? g.x : av.x * g.x;
    g.y = g.y >= 0.f ? g.y : av.y * g.y;
    g.z = g.z >= 0.f ? g.z : av.z * g.z;
    g.w = g.w >= 0.f ? g.w : av.w * g.w;
    float4 s = ((const float4*)skip)[idx];
    ((float4*)skip)[idx] = make_float4(s.x + g.x, s.y + g.y, s.z + g.z, s.w + g.w);
}

// ---------------- out = prelu(agg, a) ----------------
__global__ void k_prelu_out(const float* __restrict__ agg, const float* __restrict__ a,
                            float* __restrict__ out) {
    int idx = blockIdx.x * blockDim.x + threadIdx.x;
    if (idx >= NN * 32) return;
    int c4 = idx & 31;
    float4 av = ((const float4*)a)[c4];
    float4 g = ((const float4*)agg)[idx];
    g.x = g.x >= 0.f ? g.x : av.x * g.x;
    g.y = g.y >= 0.f ? g.y : av.y * g.y;
    g.z = g.z >= 0.f ? g.z : av.z * g.z;
    g.w = g.w >= 0.f ? g.w : av.w * g.w;
    ((float4*)out)[idx] = g;
}

extern "C" void kernel_launch(void* const* d_in, const int* in_sizes, int n_in,
                              void* d_out, int out_size) {
    const float* x  = (const float*)d_in[0];
    const int*   ei = (const int*)d_in[1];
    const float* W0 = (const float*)d_in[2];
    const float* b0 = (const float*)d_in[3];
    const float* W1 = (const float*)d_in[4];
    const float* b1 = (const float*)d_in[5];
    const float* Ws = (const float*)d_in[6];
    const float* bs = (const float*)d_in[7];
    const float* a  = (const float*)d_in[8];
    float* out = (float*)d_out;

    const int* src = ei;
    const int* dst = ei + NE;

    float *dis, *t, *skip, *agg;
    cudaGetSymbolAddress((void**)&dis, g_dis);
    cudaGetSymbolAddress((void**)&t, g_t);
    cudaGetSymbolAddress((void**)&skip, g_skip);
    cudaGetSymbolAddress((void**)&agg, g_agg);

    static bool attr_done = false;
    if (!attr_done) {
        cudaFuncSetAttribute(k_gemm_dual, cudaFuncAttributeMaxDynamicSharedMemorySize,
                             (2 * C * C + TM * C) * 4);
        cudaFuncSetAttribute(k_gemm_single, cudaFuncAttributeMaxDynamicSharedMemorySize,
                             (C * C + TM * C) * 4);
        attr_done = true;
    }

    const int EW = NN * 32;  // elementwise float4 count
    dim3 blk(256);

    // degree / symmetric norm
    k_deg_init<<<(NN + 255) / 256, blk>>>(dis);
    k_deg_count<<<(NE + 255) / 256, blk>>>(dst, dis);
    k_dis<<<(NN + 255) / 256, blk>>>(dis);

    // layer 0: t = x@W0, skip = x@Ws + bs
    k_gemm_dual<<<(NN + TM - 1) / TM, blk, (2 * C * C + TM * C) * 4>>>(x, W0, Ws, bs, t, skip);
    k_agg_init<<<(EW + 255) / 256, blk>>>(t, b0, dis, agg);
    k_scatter<<<(NE * 32 + 255) / 256, blk>>>(src, dst, dis, t, agg);
    // u = skip + prelu(agg)  (in place)
    k_prelu_add<<<(EW + 255) / 256, blk>>>(agg, a, skip);

    // layer 1: t = u@W1
    k_gemm_single<<<(NN + TM - 1) / TM, blk, (C * C + TM * C) * 4>>>(skip, W1, t);
    k_agg_init<<<(EW + 255) / 256, blk>>>(t, b1, dis, agg);
    k_scatter<<<(NE * 32 + 255) / 256, blk>>>(src, dst, dis, t, agg);
    k_prelu_out<<<(EW + 255) / 256, blk>>>(agg, a, out);
}

// round 3
// speedup vs baseline: 1.1512x; 1.1512x over previous
#include <cuda_runtime.h>

#define NN 50000
#define NE 600000
#define C  128
#define NB ((NN + 255) / 256)   // 196 scan blocks

// ---------------- scratch (static __device__, no runtime alloc) ----------------
__device__ int   g_cnt[NN];
__device__ int   g_off[NN + 1];
__device__ int   g_cur[NN];
__device__ int   g_bsum[NB];
__device__ int   g_csrc[NE];
__device__ float g_dis[NN];
__device__ float g_t[NN * C];
__device__ float g_skip[NN * C];

// ---------------- f32x2 packed-FMA helpers (sm_100) ----------------
__device__ __forceinline__ unsigned long long pk2(float lo, float hi) {
    unsigned long long r;
    asm("mov.b64 %0, {%1, %2};" : "=l"(r) : "f"(lo), "f"(hi));
    return r;
}
__device__ __forceinline__ void fma2(unsigned long long& d, unsigned long long a,
                                     unsigned long long b) {
    asm("fma.rn.f32x2 %0, %1, %2, %0;" : "+l"(d) : "l"(a), "l"(b));
}
__device__ __forceinline__ float2 unpk2(unsigned long long v) {
    float2 f;
    asm("mov.b64 {%0, %1}, %2;" : "=f"(f.x), "=f"(f.y) : "l"(v));
    return f;
}

// ---------------- degree / norm / CSR build ----------------
__global__ void k_cnt_zero() {
    int i = blockIdx.x * blockDim.x + threadIdx.x;
    if (i < NN) g_cnt[i] = 0;
}
__global__ void k_deg_count(const int* __restrict__ dst) {
    int e = blockIdx.x * blockDim.x + threadIdx.x;
    if (e < NE) atomicAdd(&g_cnt[dst[e]], 1);
}
__global__ void k_dis() {
    int i = blockIdx.x * blockDim.x + threadIdx.x;
    if (i < NN) g_dis[i] = rsqrtf((float)(g_cnt[i] + 1));  // +1 self loop
}
// blockwise exclusive scan of g_cnt -> g_off (partial) + block sums
__global__ void k_scan_a() {
    __shared__ int s[256];
    int tid = threadIdx.x;
    int i = blockIdx.x * 256 + tid;
    int v = (i < NN) ? g_cnt[i] : 0;
    s[tid] = v;
    __syncthreads();
    for (int d = 1; d < 256; d <<= 1) {
        int tv = 0;
        if (tid >= d) tv = s[tid - d];
        __syncthreads();
        if (tid >= d) s[tid] += tv;
        __syncthreads();
    }
    if (i < NN) g_off[i] = s[tid] - v;  // exclusive
    if (tid == 255) g_bsum[blockIdx.x] = s[255];
}
// scan block sums (NB <= 256) in one block
__global__ void k_scan_b() {
    __shared__ int s[256];
    int tid = threadIdx.x;
    int v = (tid < NB) ? g_bsum[tid] : 0;
    s[tid] = v;
    __syncthreads();
    for (int d = 1; d < 256; d <<= 1) {
        int tv = 0;
        if (tid >= d) tv = s[tid - d];
        __syncthreads();
        if (tid >= d) s[tid] += tv;
        __syncthreads();
    }
    if (tid < NB) g_bsum[tid] = s[tid] - v;  // exclusive
}
__global__ void k_scan_c() {
    int i = blockIdx.x * 256 + threadIdx.x;
    if (i < NN) {
        int o = g_off[i] + g_bsum[blockIdx.x];
        g_off[i] = o;
        g_cur[i] = o;
    }
    if (i == 0) g_off[NN] = NE;
}
__global__ void k_bucket(const int* __restrict__ src, const int* __restrict__ dst) {
    int e = blockIdx.x * blockDim.x + threadIdx.x;
    if (e < NE) {
        int d = dst[e];
        int p = atomicAdd(&g_cur[d], 1);
        g_csrc[p] = src[e];
    }
}

// ---------------- GEMM: out[64 rows/block] = in @ W (+bias) ----------------
// K-paired f32x2: acc[r][c] accumulates (k, k+1) lanes; reduced at epilogue.
// smem: W [128][128] 64KB + x tile [64][128] 32KB = 96KB -> 2 CTA/SM.
__global__ __launch_bounds__(256, 2) void k_gemm(const float* __restrict__ in,
                                                 const float* __restrict__ W,
                                                 const float* __restrict__ bias,
                                                 float* __restrict__ out) {
    extern __shared__ float sm[];
    float* ws = sm;           // [C][C] row-major (k, c)
    float* xs = sm + C * C;   // [64][C]
    int tid = threadIdx.x;
    int row0 = blockIdx.x * 64;

    for (int i = tid; i < C * C / 4; i += 256)
        ((float4*)ws)[i] = ((const float4*)W)[i];
    for (int i = tid; i < 64 * C / 4; i += 256) {
        int r = i >> 5;
        int gr = row0 + r;
        ((float4*)xs)[i] = (gr < NN) ? ((const float4*)in)[gr * 32 + (i & 31)]
                                     : make_float4(0.f, 0.f, 0.f, 0.f);
    }
    __syncthreads();

    int warp = tid >> 5, lane = tid & 31;
    int r0 = warp * 8;   // 8 warps x 8 rows = 64 rows
    int c0 = lane * 4;   // 32 lanes x 4 cols = 128 cols

    unsigned long long acc[8][4];
#pragma unroll
    for (int i = 0; i < 8; i++)
#pragma unroll
        for (int j = 0; j < 4; j++) acc[i][j] = 0ull;

#pragma unroll 4
    for (int kp = 0; kp < C / 2; kp++) {
        int k = kp * 2;
        float4 wk  = *(const float4*)&ws[k * C + c0];
        float4 wk1 = *(const float4*)&ws[(k + 1) * C + c0];
        unsigned long long w2[4];
        w2[0] = pk2(wk.x, wk1.x);
        w2[1] = pk2(wk.y, wk1.y);
        w2[2] = pk2(wk.z, wk1.z);
        w2[3] = pk2(wk.w, wk1.w);
#pragma unroll
        for (int i = 0; i < 8; i++) {
            unsigned long long x2 = *(const unsigned long long*)&xs[(r0 + i) * C + k];
            fma2(acc[i][0], x2, w2[0]);
            fma2(acc[i][1], x2, w2[1]);
            fma2(acc[i][2], x2, w2[2]);
            fma2(acc[i][3], x2, w2[3]);
        }
    }

    float4 bv = make_float4(0.f, 0.f, 0.f, 0.f);
    if (bias) bv = ((const float4*)bias)[lane];
#pragma unroll
    for (int i = 0; i < 8; i++) {
        int gr = row0 + r0 + i;
        if (gr < NN) {
            float2 p0 = unpk2(acc[i][0]);
            float2 p1 = unpk2(acc[i][1]);
            float2 p2 = unpk2(acc[i][2]);
            float2 p3 = unpk2(acc[i][3]);
            *(float4*)&out[gr * C + c0] =
                make_float4(p0.x + p0.y + bv.x, p1.x + p1.y + bv.y,
                            p2.x + p2.y + bv.z, p3.x + p3.y + bv.w);
        }
    }
}

// ---------------- CSR gather: one warp per node, no atomics ----------------
// acc = b + t[node]*dis^2 (bias + self loop), then += t[src]*dis[src]*dis[node]
// mode 0: skip_io <- skip_io + prelu(acc)   (produces u in place)
// mode 1: out <- prelu(acc)                 (final output)
__global__ __launch_bounds__(256) void k_gather(const float* __restrict__ t,
                                                const float* __restrict__ b,
                                                const float* __restrict__ a,
                                                float* __restrict__ skip_io,
                                                float* __restrict__ out, int mode) {
    int node = (blockIdx.x * 256 + threadIdx.x) >> 5;
    int lane = threadIdx.x & 31;
    if (node >= NN) return;

    float di = g_dis[node];
    float d2 = di * di;
    float4 bv = ((const float4*)b)[lane];
    float4 tv = ((const float4*)t)[node * 32 + lane];
    float4 acc = make_float4(bv.x + tv.x * d2, bv.y + tv.y * d2,
                             bv.z + tv.z * d2, bv.w + tv.w * d2);

    int beg = g_off[node], end = g_off[node + 1];
    for (int base = beg; base < end; base += 32) {
        int idx = base + lane;
        int s = 0;
        float w = 0.f;
        if (idx < end) {
            s = g_csrc[idx];
            w = g_dis[s] * di;
        }
        int cnt = min(32, end - base);
        for (int j = 0; j < cnt; j++) {
            int sj = __shfl_sync(0xffffffffu, s, j);
            float wj = __shfl_sync(0xffffffffu, w, j);
            float4 v = ((const float4*)t)[sj * 32 + lane];
            acc.x += v.x * wj;
            acc.y += v.y * wj;
            acc.z += v.z * wj;
            acc.w += v.w * wj;
        }
    }

    float4 av = ((const float4*)a)[lane];
    float4 p;
    p.x = acc.x >= 0.f ? acc.x : av.x * acc.x;
    p.y = acc.y >= 0.f ? acc.y : av.y * acc.y;
    p.z = acc.z >= 0.f ? acc.z : av.z * acc.z;
    p.w = acc.w >= 0.f ? acc.w : av.w * acc.w;

    if (mode == 0) {
        float4 sk = ((const float4*)skip_io)[node * 32 + lane];
        ((float4*)skip_io)[node * 32 + lane] =
            make_float4(sk.x + p.x, sk.y + p.y, sk.z + p.z, sk.w + p.w);
    } else {
        ((float4*)out)[node * 32 + lane] = p;
    }
}

extern "C" void kernel_launch(void* const* d_in, const int* in_sizes, int n_in,
                              void* d_out, int out_size) {
    const float* x  = (const float*)d_in[0];
    const int*   ei = (const int*)d_in[1];
    const float* W0 = (const float*)d_in[2];
    const float* b0 = (const float*)d_in[3];
    const float* W1 = (const float*)d_in[4];
    const float* b1 = (const float*)d_in[5];
    const float* Ws = (const float*)d_in[6];
    const float* bs = (const float*)d_in[7];
    const float* a  = (const float*)d_in[8];
    float* out = (float*)d_out;

    const int* src = ei;
    const int* dst = ei + NE;

    float *t, *skip;
    cudaGetSymbolAddress((void**)&t, g_t);
    cudaGetSymbolAddress((void**)&skip, g_skip);

    const int GEMM_SMEM = (C * C + 64 * C) * 4;  // 96KB
    cudaFuncSetAttribute(k_gemm, cudaFuncAttributeMaxDynamicSharedMemorySize,
                         GEMM_SMEM);

    // ---- degree / norm / CSR ----
    k_cnt_zero<<<NB, 256>>>();
    k_deg_count<<<(NE + 255) / 256, 256>>>(dst);
    k_dis<<<NB, 256>>>();
    k_scan_a<<<NB, 256>>>();
    k_scan_b<<<1, 256>>>();
    k_scan_c<<<NB, 256>>>();
    k_bucket<<<(NE + 255) / 256, 256>>>(src, dst);

    const int GEMM_GRID = (NN + 63) / 64;
    const int GATHER_GRID = (NN * 32 + 255) / 256;

    // ---- layer 0 ----
    k_gemm<<<GEMM_GRID, 256, GEMM_SMEM>>>(x, Ws, bs, skip);      // skip = x@Ws + bs
    k_gemm<<<GEMM_GRID, 256, GEMM_SMEM>>>(x, W0, nullptr, t);    // t = x@W0
    k_gather<<<GATHER_GRID, 256>>>(t, b0, a, skip, nullptr, 0);  // skip = u

    // ---- layer 1 ----
    k_gemm<<<GEMM_GRID, 256, GEMM_SMEM>>>(skip, W1, nullptr, t); // t = u@W1
    k_gather<<<GATHER_GRID, 256>>>(t, b1, a, nullptr, out, 1);   // out = prelu(agg)
}

// round 4
// speedup vs baseline: 1.3886x; 1.2062x over previous
#include <cuda_runtime.h>

#define NN 50000
#define NE 600000
#define C  128
#define NB ((NN + 255) / 256)   // 196 scan blocks

// ---------------- scratch (static __device__, no runtime alloc) ----------------
__device__ int   g_cnt[NN];
__device__ int   g_off[NN + 1];
__device__ int   g_cur[NN];
__device__ int   g_bsum[NB];
__device__ int   g_csrc[NE];
__device__ float g_dis[NN];
__device__ float g_t[NN * C];
__device__ float g_skip[NN * C];

// ---------------- f32x2 packed-FMA helpers (sm_100) ----------------
__device__ __forceinline__ unsigned long long pk2(float lo, float hi) {
    unsigned long long r;
    asm("mov.b64 %0, {%1, %2};" : "=l"(r) : "f"(lo), "f"(hi));
    return r;
}
__device__ __forceinline__ void fma2(unsigned long long& d, unsigned long long a,
                                     unsigned long long b) {
    asm("fma.rn.f32x2 %0, %1, %2, %0;" : "+l"(d) : "l"(a), "l"(b));
}
__device__ __forceinline__ float2 unpk2(unsigned long long v) {
    float2 f;
    asm("mov.b64 {%0, %1}, %2;" : "=f"(f.x), "=f"(f.y) : "l"(v));
    return f;
}

// ---------------- CSR build ----------------
__global__ void k_zero() {
    int i = blockIdx.x * blockDim.x + threadIdx.x;
    if (i < NN) g_cnt[i] = 0;
}
// 4 edges per thread (NE % 4 == 0)
__global__ void k_deg_count(const int4* __restrict__ dst4) {
    int i = blockIdx.x * blockDim.x + threadIdx.x;
    if (i < NE / 4) {
        int4 d = dst4[i];
        atomicAdd(&g_cnt[d.x], 1);
        atomicAdd(&g_cnt[d.y], 1);
        atomicAdd(&g_cnt[d.z], 1);
        atomicAdd(&g_cnt[d.w], 1);
    }
}
__global__ void k_scan_a() {
    __shared__ int s[256];
    int tid = threadIdx.x;
    int i = blockIdx.x * 256 + tid;
    int v = (i < NN) ? g_cnt[i] : 0;
    s[tid] = v;
    __syncthreads();
    for (int d = 1; d < 256; d <<= 1) {
        int tv = 0;
        if (tid >= d) tv = s[tid - d];
        __syncthreads();
        if (tid >= d) s[tid] += tv;
        __syncthreads();
    }
    if (i < NN) g_off[i] = s[tid] - v;  // exclusive, block-local
    if (tid == 255) g_bsum[blockIdx.x] = s[255];
}
__global__ void k_scan_b() {
    __shared__ int s[256];
    int tid = threadIdx.x;
    int v = (tid < NB) ? g_bsum[tid] : 0;
    s[tid] = v;
    __syncthreads();
    for (int d = 1; d < 256; d <<= 1) {
        int tv = 0;
        if (tid >= d) tv = s[tid - d];
        __syncthreads();
        if (tid >= d) s[tid] += tv;
        __syncthreads();
    }
    if (tid < NB) g_bsum[tid] = s[tid] - v;  // exclusive
}
// finalize offsets + cur + dis (fused)
__global__ void k_scan_c() {
    int i = blockIdx.x * 256 + threadIdx.x;
    if (i < NN) {
        int o = g_off[i] + g_bsum[blockIdx.x];
        g_off[i] = o;
        g_cur[i] = o;
        g_dis[i] = rsqrtf((float)(g_cnt[i] + 1));  // +1 self loop
    }
    if (i == 0) g_off[NN] = NE;
}
__global__ void k_bucket(const int4* __restrict__ src4, const int4* __restrict__ dst4) {
    int i = blockIdx.x * blockDim.x + threadIdx.x;
    if (i < NE / 4) {
        int4 s = src4[i];
        int4 d = dst4[i];
        int p;
        p = atomicAdd(&g_cur[d.x], 1); g_csrc[p] = s.x;
        p = atomicAdd(&g_cur[d.y], 1); g_csrc[p] = s.y;
        p = atomicAdd(&g_cur[d.z], 1); g_csrc[p] = s.z;
        p = atomicAdd(&g_cur[d.w], 1); g_csrc[p] = s.w;
    }
}

// ---------------- GEMM: out[64 rows/block] = in @ W (+bias) ----------------
// W pre-packed in smem as k-paired f32x2: wp[kp*C + c] = (W[2kp][c], W[2kp+1][c]).
// Inner loop: pure LDS + FFMA2, no packing ops. smem = 64KB(wp) + 32KB(x) = 96KB.
__global__ __launch_bounds__(256, 2) void k_gemm(const float* __restrict__ in,
                                                 const float* __restrict__ W,
                                                 const float* __restrict__ bias,
                                                 float* __restrict__ out) {
    extern __shared__ float sm[];
    unsigned long long* wp = (unsigned long long*)sm;  // [64][128] packed, 64KB
    float* xs = sm + 16384;                            // [64][128], 32KB
    int tid = threadIdx.x;
    int row0 = blockIdx.x * 64;

    // pack W (coalesced float4 reads of two adjacent k-rows)
    for (int g = tid; g < (C / 2) * (C / 4); g += 256) {  // 2048 groups
        int kp = g >> 5;
        int cg = (g & 31) << 2;
        float4 wa = *(const float4*)&W[(2 * kp) * C + cg];
        float4 wb = *(const float4*)&W[(2 * kp + 1) * C + cg];
        ulonglong2 p0, p1;
        p0.x = pk2(wa.x, wb.x);
        p0.y = pk2(wa.y, wb.y);
        p1.x = pk2(wa.z, wb.z);
        p1.y = pk2(wa.w, wb.w);
        *(ulonglong2*)&wp[kp * C + cg] = p0;
        *(ulonglong2*)&wp[kp * C + cg + 2] = p1;
    }
    for (int i = tid; i < 64 * C / 4; i += 256) {
        int r = i >> 5;
        int gr = row0 + r;
        ((float4*)xs)[i] = (gr < NN) ? ((const float4*)in)[gr * 32 + (i & 31)]
                                     : make_float4(0.f, 0.f, 0.f, 0.f);
    }
    __syncthreads();

    int warp = tid >> 5, lane = tid & 31;
    int r0 = warp * 8;   // 8 warps x 8 rows
    int c0 = lane * 4;   // 32 lanes x 4 cols

    unsigned long long acc[8][4];
#pragma unroll
    for (int i = 0; i < 8; i++)
#pragma unroll
        for (int j = 0; j < 4; j++) acc[i][j] = 0ull;

#pragma unroll 4
    for (int kp = 0; kp < C / 2; kp++) {
        ulonglong2 wA = *(ulonglong2*)&wp[kp * C + c0];
        ulonglong2 wB = *(ulonglong2*)&wp[kp * C + c0 + 2];
#pragma unroll
        for (int i = 0; i < 8; i++) {
            unsigned long long x2 =
                *(const unsigned long long*)&xs[(r0 + i) * C + 2 * kp];
            fma2(acc[i][0], x2, wA.x);
            fma2(acc[i][1], x2, wA.y);
            fma2(acc[i][2], x2, wB.x);
            fma2(acc[i][3], x2, wB.y);
        }
    }

    float4 bv = make_float4(0.f, 0.f, 0.f, 0.f);
    if (bias) bv = ((const float4*)bias)[lane];
#pragma unroll
    for (int i = 0; i < 8; i++) {
        int gr = row0 + r0 + i;
        if (gr < NN) {
            float2 p0 = unpk2(acc[i][0]);
            float2 p1 = unpk2(acc[i][1]);
            float2 p2 = unpk2(acc[i][2]);
            float2 p3 = unpk2(acc[i][3]);
            *(float4*)&out[gr * C + c0] =
                make_float4(p0.x + p0.y + bv.x, p1.x + p1.y + bv.y,
                            p2.x + p2.y + bv.z, p3.x + p3.y + bv.w);
        }
    }
}

// ---------------- CSR gather: one warp per node, edge loop unrolled x4 ----------------
// acc = b + t[node]*dis^2, then += t[src]*dis[src]*dis[node] over CSR row.
// mode 0: skip_io += prelu(acc); mode 1: out = prelu(acc)
__global__ __launch_bounds__(256) void k_gather(const float* __restrict__ t,
                                                const float* __restrict__ b,
                                                const float* __restrict__ a,
                                                float* __restrict__ skip_io,
                                                float* __restrict__ out, int mode) {
    int node = (blockIdx.x * 256 + threadIdx.x) >> 5;
    int lane = threadIdx.x & 31;
    if (node >= NN) return;

    float di = g_dis[node];
    float d2 = di * di;
    float4 bv = ((const float4*)b)[lane];
    float4 tv = ((const float4*)t)[node * 32 + lane];
    float4 acc = make_float4(bv.x + tv.x * d2, bv.y + tv.y * d2,
                             bv.z + tv.z * d2, bv.w + tv.w * d2);

    int beg = g_off[node], end = g_off[node + 1];
    for (int base = beg; base < end; base += 32) {
        int idx = base + lane;
        int s = 0;
        float w = 0.f;
        if (idx < end) {
            s = g_csrc[idx];
            w = g_dis[s] * di;
        }
        int cnt = min(32, end - base);
        int j = 0;
        for (; j + 4 <= cnt; j += 4) {
            int s0 = __shfl_sync(0xffffffffu, s, j);
            int s1 = __shfl_sync(0xffffffffu, s, j + 1);
            int s2 = __shfl_sync(0xffffffffu, s, j + 2);
            int s3 = __shfl_sync(0xffffffffu, s, j + 3);
            float w0 = __shfl_sync(0xffffffffu, w, j);
            float w1 = __shfl_sync(0xffffffffu, w, j + 1);
            float w2 = __shfl_sync(0xffffffffu, w, j + 2);
            float w3 = __shfl_sync(0xffffffffu, w, j + 3);
            float4 v0 = ((const float4*)t)[s0 * 32 + lane];
            float4 v1 = ((const float4*)t)[s1 * 32 + lane];
            float4 v2 = ((const float4*)t)[s2 * 32 + lane];
            float4 v3 = ((const float4*)t)[s3 * 32 + lane];
            acc.x += v0.x * w0; acc.y += v0.y * w0; acc.z += v0.z * w0; acc.w += v0.w * w0;
            acc.x += v1.x * w1; acc.y += v1.y * w1; acc.z += v1.z * w1; acc.w += v1.w * w1;
            acc.x += v2.x * w2; acc.y += v2.y * w2; acc.z += v2.z * w2; acc.w += v2.w * w2;
            acc.x += v3.x * w3; acc.y += v3.y * w3; acc.z += v3.z * w3; acc.w += v3.w * w3;
        }
        for (; j < cnt; j++) {
            int sj = __shfl_sync(0xffffffffu, s, j);
            float wj = __shfl_sync(0xffffffffu, w, j);
            float4 v = ((const float4*)t)[sj * 32 + lane];
            acc.x += v.x * wj; acc.y += v.y * wj; acc.z += v.z * wj; acc.w += v.w * wj;
        }
    }

    float4 av = ((const float4*)a)[lane];
    float4 p;
    p.x = acc.x >= 0.f ? acc.x : av.x * acc.x;
    p.y = acc.y >= 0.f ? acc.y : av.y * acc.y;
    p.z = acc.z >= 0.f ? acc.z : av.z * acc.z;
    p.w = acc.w >= 0.f ? acc.w : av.w * acc.w;

    if (mode == 0) {
        float4 sk = ((const float4*)skip_io)[node * 32 + lane];
        ((float4*)skip_io)[node * 32 + lane] =
            make_float4(sk.x + p.x, sk.y + p.y, sk.z + p.z, sk.w + p.w);
    } else {
        ((float4*)out)[node * 32 + lane] = p;
    }
}

extern "C" void kernel_launch(void* const* d_in, const int* in_sizes, int n_in,
                              void* d_out, int out_size) {
    const float* x  = (const float*)d_in[0];
    const int*   ei = (const int*)d_in[1];
    const float* W0 = (const float*)d_in[2];
    const float* b0 = (const float*)d_in[3];
    const float* W1 = (const float*)d_in[4];
    const float* b1 = (const float*)d_in[5];
    const float* Ws = (const float*)d_in[6];
    const float* bs = (const float*)d_in[7];
    const float* a  = (const float*)d_in[8];
    float* out = (float*)d_out;

    const int4* src4 = (const int4*)ei;
    const int4* dst4 = (const int4*)(ei + NE);

    float *t, *skip;
    cudaGetSymbolAddress((void**)&t, g_t);
    cudaGetSymbolAddress((void**)&skip, g_skip);

    const int GEMM_SMEM = (C * C + 64 * C) * 4;  // 96KB
    cudaFuncSetAttribute(k_gemm, cudaFuncAttributeMaxDynamicSharedMemorySize,
                         GEMM_SMEM);

    const int GEMM_GRID = (NN + 63) / 64;
    const int GATHER_GRID = (NN * 32 + 255) / 256;
    const int E4 = NE / 4;

    // launches 0..4: CSR prefix (so launch #5, the ncu capture slot, is k_gemm)
    k_zero<<<NB, 256>>>();                                        // 0
    k_deg_count<<<(E4 + 255) / 256, 256>>>(dst4);                 // 1
    k_scan_a<<<NB, 256>>>();                                      // 2
    k_scan_b<<<1, 256>>>();                                       // 3
    k_scan_c<<<NB, 256>>>();                                      // 4

    // layer 0 GEMMs (5, 6)
    k_gemm<<<GEMM_GRID, 256, GEMM_SMEM>>>(x, Ws, bs, skip);       // 5: skip = x@Ws+bs
    k_gemm<<<GEMM_GRID, 256, GEMM_SMEM>>>(x, W0, nullptr, t);     // 6: t = x@W0

    // finish CSR (needs scan_c), then aggregate
    k_bucket<<<(E4 + 255) / 256, 256>>>(src4, dst4);              // 7
    k_gather<<<GATHER_GRID, 256>>>(t, b0, a, skip, nullptr, 0);   // 8: skip = u

    // layer 1
    k_gemm<<<GEMM_GRID, 256, GEMM_SMEM>>>(skip, W1, nullptr, t);  // 9: t = u@W1
    k_gather<<<GATHER_GRID, 256>>>(t, b1, a, nullptr, out, 1);    // 10: out
}

// round 5
// speedup vs baseline: 1.3999x; 1.0081x over previous
#include <cuda_runtime.h>

#define NN 50000
#define NE 600000
#define C  128
#define NB ((NN + 255) / 256)   // 196 scan blocks

// ---------------- scratch (static __device__, zero-initialized at load) ----------------
__device__ int   g_cnt[NN];      // stays zero between pipeline runs (bucket re-zeros)
__device__ int   g_off[NN + 1];
__device__ int   g_cur[NN];
__device__ int   g_bsum[NB];
__device__ int   g_csrc[NE];
__device__ float g_dis[NN];
__device__ float g_t[NN * C];
__device__ float g_skip[NN * C];

// ---------------- f32x2 packed-FMA helpers (sm_100) ----------------
__device__ __forceinline__ unsigned long long pk2(float lo, float hi) {
    unsigned long long r;
    asm("mov.b64 %0, {%1, %2};" : "=l"(r) : "f"(lo), "f"(hi));
    return r;
}
__device__ __forceinline__ void fma2(unsigned long long& d, unsigned long long a,
                                     unsigned long long b) {
    asm("fma.rn.f32x2 %0, %1, %2, %0;" : "+l"(d) : "l"(a), "l"(b));
}
__device__ __forceinline__ float2 unpk2(unsigned long long v) {
    float2 f;
    asm("mov.b64 {%0, %1}, %2;" : "=f"(f.x), "=f"(f.y) : "l"(v));
    return f;
}

// ---------------- CSR build ----------------
// 4 edges per thread (NE % 4 == 0); g_cnt must be zero on entry (BSS init /
// re-zeroed by k_bucket at the end of every pipeline run).
__global__ void k_deg_count(const int4* __restrict__ dst4) {
    int i = blockIdx.x * blockDim.x + threadIdx.x;
    if (i < NE / 4) {
        int4 d = dst4[i];
        atomicAdd(&g_cnt[d.x], 1);
        atomicAdd(&g_cnt[d.y], 1);
        atomicAdd(&g_cnt[d.z], 1);
        atomicAdd(&g_cnt[d.w], 1);
    }
}
__global__ void k_scan_a() {
    __shared__ int s[256];
    int tid = threadIdx.x;
    int i = blockIdx.x * 256 + tid;
    int v = (i < NN) ? g_cnt[i] : 0;
    s[tid] = v;
    __syncthreads();
    for (int d = 1; d < 256; d <<= 1) {
        int tv = 0;
        if (tid >= d) tv = s[tid - d];
        __syncthreads();
        if (tid >= d) s[tid] += tv;
        __syncthreads();
    }
    if (i < NN) g_off[i] = s[tid] - v;  // exclusive, block-local
    if (tid == 255) g_bsum[blockIdx.x] = s[255];
}
// finalize: add prefix of block sums (reduced in-block), init cur, compute dis
__global__ void k_scan_c() {
    __shared__ int red[256];
    int tid = threadIdx.x, bid = blockIdx.x;
    red[tid] = (tid < bid && tid < NB) ? g_bsum[tid] : 0;
    __syncthreads();
    for (int d = 128; d > 0; d >>= 1) {
        if (tid < d) red[tid] += red[tid + d];
        __syncthreads();
    }
    int base = red[0];
    int i = bid * 256 + tid;
    if (i < NN) {
        int o = g_off[i] + base;
        g_off[i] = o;
        g_cur[i] = o;
        g_dis[i] = rsqrtf((float)(g_cnt[i] + 1));  // +1 self loop
    }
    if (i == 0) g_off[NN] = NE;
}
// bucket edges by dst; also re-zero g_cnt for the next pipeline run
__global__ void k_bucket(const int4* __restrict__ src4, const int4* __restrict__ dst4) {
    int i = blockIdx.x * blockDim.x + threadIdx.x;
    if (i < NE / 4) {
        int4 s = src4[i];
        int4 d = dst4[i];
        int p;
        p = atomicAdd(&g_cur[d.x], 1); g_csrc[p] = s.x;
        p = atomicAdd(&g_cur[d.y], 1); g_csrc[p] = s.y;
        p = atomicAdd(&g_cur[d.z], 1); g_csrc[p] = s.z;
        p = atomicAdd(&g_cur[d.w], 1); g_csrc[p] = s.w;
    }
    if (i < NN / 4) ((int4*)g_cnt)[i] = make_int4(0, 0, 0, 0);
}

// ---------------- GEMM: out[64 rows/block] = in @ W (+bias) ----------------
// W pre-packed in smem as k-paired f32x2; inner loop unrolled over 4 k's so x
// comes in as one broadcast LDS.128 per row (smem slots: 24 per 64 FFMA2).
__global__ __launch_bounds__(256, 2) void k_gemm(const float* __restrict__ in,
                                                 const float* __restrict__ W,
                                                 const float* __restrict__ bias,
                                                 float* __restrict__ out) {
    extern __shared__ float sm[];
    unsigned long long* wp = (unsigned long long*)sm;  // [64][128] packed, 64KB
    float* xs = sm + 16384;                            // [64][128], 32KB
    int tid = threadIdx.x;
    int row0 = blockIdx.x * 64;

    // pack W (coalesced float4 reads of two adjacent k-rows)
    for (int g = tid; g < (C / 2) * (C / 4); g += 256) {  // 2048 groups
        int kp = g >> 5;
        int cg = (g & 31) << 2;
        float4 wa = *(const float4*)&W[(2 * kp) * C + cg];
        float4 wb = *(const float4*)&W[(2 * kp + 1) * C + cg];
        ulonglong2 p0, p1;
        p0.x = pk2(wa.x, wb.x);
        p0.y = pk2(wa.y, wb.y);
        p1.x = pk2(wa.z, wb.z);
        p1.y = pk2(wa.w, wb.w);
        *(ulonglong2*)&wp[kp * C + cg] = p0;
        *(ulonglong2*)&wp[kp * C + cg + 2] = p1;
    }
    for (int i = tid; i < 64 * C / 4; i += 256) {
        int r = i >> 5;
        int gr = row0 + r;
        ((float4*)xs)[i] = (gr < NN) ? ((const float4*)in)[gr * 32 + (i & 31)]
                                     : make_float4(0.f, 0.f, 0.f, 0.f);
    }
    __syncthreads();

    int warp = tid >> 5, lane = tid & 31;
    int r0 = warp * 8;   // 8 warps x 8 rows
    int c0 = lane * 4;   // 32 lanes x 4 cols

    unsigned long long acc[8][4];
#pragma unroll
    for (int i = 0; i < 8; i++)
#pragma unroll
        for (int j = 0; j < 4; j++) acc[i][j] = 0ull;

#pragma unroll 2
    for (int kq = 0; kq < C / 4; kq++) {  // 4 k's per iteration
        int kp0 = 2 * kq;
        ulonglong2 w0A = *(ulonglong2*)&wp[kp0 * C + c0];
        ulonglong2 w0B = *(ulonglong2*)&wp[kp0 * C + c0 + 2];
        ulonglong2 w1A = *(ulonglong2*)&wp[(kp0 + 1) * C + c0];
        ulonglong2 w1B = *(ulonglong2*)&wp[(kp0 + 1) * C + c0 + 2];
#pragma unroll
        for (int i = 0; i < 8; i++) {
            ulonglong2 x4 = *(const ulonglong2*)&xs[(r0 + i) * C + 4 * kq];
            fma2(acc[i][0], x4.x, w0A.x);
            fma2(acc[i][1], x4.x, w0A.y);
            fma2(acc[i][2], x4.x, w0B.x);
            fma2(acc[i][3], x4.x, w0B.y);
            fma2(acc[i][0], x4.y, w1A.x);
            fma2(acc[i][1], x4.y, w1A.y);
            fma2(acc[i][2], x4.y, w1B.x);
            fma2(acc[i][3], x4.y, w1B.y);
        }
    }

    float4 bv = make_float4(0.f, 0.f, 0.f, 0.f);
    if (bias) bv = ((const float4*)bias)[lane];
#pragma unroll
    for (int i = 0; i < 8; i++) {
        int gr = row0 + r0 + i;
        if (gr < NN) {
            float2 p0 = unpk2(acc[i][0]);
            float2 p1 = unpk2(acc[i][1]);
            float2 p2 = unpk2(acc[i][2]);
            float2 p3 = unpk2(acc[i][3]);
            *(float4*)&out[gr * C + c0] =
                make_float4(p0.x + p0.y + bv.x, p1.x + p1.y + bv.y,
                            p2.x + p2.y + bv.z, p3.x + p3.y + bv.w);
        }
    }
}

// ---------------- CSR gather: one warp per node, edge loop unrolled x4 ----------------
__global__ __launch_bounds__(256) void k_gather(const float* __restrict__ t,
                                                const float* __restrict__ b,
                                                const float* __restrict__ a,
                                                float* __restrict__ skip_io,
                                                float* __restrict__ out, int mode) {
    int node = (blockIdx.x * 256 + threadIdx.x) >> 5;
    int lane = threadIdx.x & 31;
    if (node >= NN) return;

    float di = g_dis[node];
    float d2 = di * di;
    float4 bv = ((const float4*)b)[lane];
    float4 tv = ((const float4*)t)[node * 32 + lane];
    float4 acc = make_float4(bv.x + tv.x * d2, bv.y + tv.y * d2,
                             bv.z + tv.z * d2, bv.w + tv.w * d2);

    int beg = g_off[node], end = g_off[node + 1];
    for (int base = beg; base < end; base += 32) {
        int idx = base + lane;
        int s = 0;
        float w = 0.f;
        if (idx < end) {
            s = g_csrc[idx];
            w = g_dis[s] * di;
        }
        int cnt = min(32, end - base);
        int j = 0;
        for (; j + 4 <= cnt; j += 4) {
            int s0 = __shfl_sync(0xffffffffu, s, j);
            int s1 = __shfl_sync(0xffffffffu, s, j + 1);
            int s2 = __shfl_sync(0xffffffffu, s, j + 2);
            int s3 = __shfl_sync(0xffffffffu, s, j + 3);
            float w0 = __shfl_sync(0xffffffffu, w, j);
            float w1 = __shfl_sync(0xffffffffu, w, j + 1);
            float w2 = __shfl_sync(0xffffffffu, w, j + 2);
            float w3 = __shfl_sync(0xffffffffu, w, j + 3);
            float4 v0 = ((const float4*)t)[s0 * 32 + lane];
            float4 v1 = ((const float4*)t)[s1 * 32 + lane];
            float4 v2 = ((const float4*)t)[s2 * 32 + lane];
            float4 v3 = ((const float4*)t)[s3 * 32 + lane];
            acc.x += v0.x * w0; acc.y += v0.y * w0; acc.z += v0.z * w0; acc.w += v0.w * w0;
            acc.x += v1.x * w1; acc.y += v1.y * w1; acc.z += v1.z * w1; acc.w += v1.w * w1;
            acc.x += v2.x * w2; acc.y += v2.y * w2; acc.z += v2.z * w2; acc.w += v2.w * w2;
            acc.x += v3.x * w3; acc.y += v3.y * w3; acc.z += v3.z * w3; acc.w += v3.w * w3;
        }
        for (; j < cnt; j++) {
            int sj = __shfl_sync(0xffffffffu, s, j);
            float wj = __shfl_sync(0xffffffffu, w, j);
            float4 v = ((const float4*)t)[sj * 32 + lane];
            acc.x += v.x * wj; acc.y += v.y * wj; acc.z += v.z * wj; acc.w += v.w * wj;
        }
    }

    float4 av = ((const float4*)a)[lane];
    float4 p;
    p.x = acc.x >= 0.f ? acc.x : av.x * acc.x;
    p.y = acc.y >= 0.f ? acc.y : av.y * acc.y;
    p.z = acc.z >= 0.f ? acc.z : av.z * acc.z;
    p.w = acc.w >= 0.f ? acc.w : av.w * acc.w;

    if (mode == 0) {
        float4 sk = ((const float4*)skip_io)[node * 32 + lane];
        ((float4*)skip_io)[node * 32 + lane] =
            make_float4(sk.x + p.x, sk.y + p.y, sk.z + p.z, sk.w + p.w);
    } else {
        ((float4*)out)[node * 32 + lane] = p;
    }
}

extern "C" void kernel_launch(void* const* d_in, const int* in_sizes, int n_in,
                              void* d_out, int out_size) {
    const float* x  = (const float*)d_in[0];
    const int*   ei = (const int*)d_in[1];
    const float* W0 = (const float*)d_in[2];
    const float* b0 = (const float*)d_in[3];
    const float* W1 = (const float*)d_in[4];
    const float* b1 = (const float*)d_in[5];
    const float* Ws = (const float*)d_in[6];
    const float* bs = (const float*)d_in[7];
    const float* a  = (const float*)d_in[8];
    float* out = (float*)d_out;

    const int4* src4 = (const int4*)ei;
    const int4* dst4 = (const int4*)(ei + NE);

    float *t, *skip;
    cudaGetSymbolAddress((void**)&t, g_t);
    cudaGetSymbolAddress((void**)&skip, g_skip);

    const int GEMM_SMEM = (C * C + 64 * C) * 4;  // 96KB
    cudaFuncSetAttribute(k_gemm, cudaFuncAttributeMaxDynamicSharedMemorySize,
                         GEMM_SMEM);

    const int GEMM_GRID = (NN + 63) / 64;
    const int GATHER_GRID = (NN * 32 + 255) / 256;
    const int E4 = NE / 4;

    // 9 launches; index 3 (ncu capture slot) = first k_gemm
    k_deg_count<<<(E4 + 255) / 256, 256>>>(dst4);                 // 0
    k_scan_a<<<NB, 256>>>();                                      // 1
    k_scan_c<<<NB, 256>>>();                                      // 2

    k_gemm<<<GEMM_GRID, 256, GEMM_SMEM>>>(x, Ws, bs, skip);       // 3: skip = x@Ws+bs  [ncu]
    k_gemm<<<GEMM_GRID, 256, GEMM_SMEM>>>(x, W0, nullptr, t);     // 4: t = x@W0

    k_bucket<<<(E4 + 255) / 256, 256>>>(src4, dst4);              // 5 (also re-zeros g_cnt)
    k_gather<<<GATHER_GRID, 256>>>(t, b0, a, skip, nullptr, 0);   // 6: skip = u

    k_gemm<<<GEMM_GRID, 256, GEMM_SMEM>>>(skip, W1, nullptr, t);  // 7: t = u@W1
    k_gather<<<GATHER_GRID, 256>>>(t, b1, a, nullptr, out, 1);    // 8: out
}

// round 8
// speedup vs baseline: 1.4582x; 1.0417x over previous
#include <cuda_runtime.h>

#define NN 50000
#define NE 600000
#define C  128
#define NB ((NN + 255) / 256)   // 196 scan blocks

// ---------------- scratch (static __device__, zero-initialized at load) ----------------
__device__ int   g_cnt[NN];      // stays zero between pipeline runs (bucket re-zeros)
__device__ int   g_off[NN + 1];
__device__ int   g_cur[NN];
__device__ int   g_bsum[NB];
__device__ int   g_csrc[NE];
__device__ float g_dis[NN];
__device__ float g_t[NN * C];
__device__ float g_skip[NN * C];

// ---------------- f32x2 packed-FMA helpers (sm_100) ----------------
__device__ __forceinline__ unsigned long long pk2(float lo, float hi) {
    unsigned long long r;
    asm("mov.b64 %0, {%1, %2};" : "=l"(r) : "f"(lo), "f"(hi));
    return r;
}
__device__ __forceinline__ void fma2(unsigned long long& d, unsigned long long a,
                                     unsigned long long b) {
    asm("fma.rn.f32x2 %0, %1, %2, %0;" : "+l"(d) : "l"(a), "l"(b));
}
__device__ __forceinline__ float2 unpk2(unsigned long long v) {
    float2 f;
    asm("mov.b64 {%0, %1}, %2;" : "=f"(f.x), "=f"(f.y) : "l"(v));
    return f;
}

// ---------------- CSR build ----------------
__global__ void k_deg_count(const int4* __restrict__ dst4) {
    int i = blockIdx.x * blockDim.x + threadIdx.x;
    if (i < NE / 4) {
        int4 d = dst4[i];
        atomicAdd(&g_cnt[d.x], 1);
        atomicAdd(&g_cnt[d.y], 1);
        atomicAdd(&g_cnt[d.z], 1);
        atomicAdd(&g_cnt[d.w], 1);
    }
}
__global__ void k_scan_a() {
    __shared__ int s[256];
    int tid = threadIdx.x;
    int i = blockIdx.x * 256 + tid;
    int v = (i < NN) ? g_cnt[i] : 0;
    s[tid] = v;
    __syncthreads();
    for (int d = 1; d < 256; d <<= 1) {
        int tv = 0;
        if (tid >= d) tv = s[tid - d];
        __syncthreads();
        if (tid >= d) s[tid] += tv;
        __syncthreads();
    }
    if (i < NN) g_off[i] = s[tid] - v;  // exclusive, block-local
    if (tid == 255) g_bsum[blockIdx.x] = s[255];
}
__global__ void k_scan_c() {
    __shared__ int red[256];
    int tid = threadIdx.x, bid = blockIdx.x;
    red[tid] = (tid < bid && tid < NB) ? g_bsum[tid] : 0;
    __syncthreads();
    for (int d = 128; d > 0; d >>= 1) {
        if (tid < d) red[tid] += red[tid + d];
        __syncthreads();
    }
    int base = red[0];
    int i = bid * 256 + tid;
    if (i < NN) {
        int o = g_off[i] + base;
        g_off[i] = o;
        g_cur[i] = o;
        g_dis[i] = rsqrtf((float)(g_cnt[i] + 1));  // +1 self loop
    }
    if (i == 0) g_off[NN] = NE;
}
__global__ void k_bucket(const int4* __restrict__ src4, const int4* __restrict__ dst4) {
    int i = blockIdx.x * blockDim.x + threadIdx.x;
    if (i < NE / 4) {
        int4 s = src4[i];
        int4 d = dst4[i];
        int p;
        p = atomicAdd(&g_cur[d.x], 1); g_csrc[p] = s.x;
        p = atomicAdd(&g_cur[d.y], 1); g_csrc[p] = s.y;
        p = atomicAdd(&g_cur[d.z], 1); g_csrc[p] = s.z;
        p = atomicAdd(&g_cur[d.w], 1); g_csrc[p] = s.w;
    }
    if (i < NN / 4) ((int4*)g_cnt)[i] = make_int4(0, 0, 0, 0);
}

// ---------------- GEMM: out[64 rows/block] = in @ W (+bias) ----------------
// Packed-W smem layout, LANE-CONTIGUOUS to kill bank conflicts:
//   per k-pair kp (u64 units, row = 128 u64 = 1024B):
//     [kp*128 +      2l .. 2l+1] = f32x2 cols (4l, 4l+1)   <- lane l chunk A
//     [kp*128 + 64 + 2l .. 2l+1] = f32x2 cols (4l+2, 4l+3) <- lane l chunk B
//   LDS.128 at byte l*16 (A) / 512 + l*16 (B): stride-16B sequential, 4 phases, 0 conflicts.
__global__ __launch_bounds__(256, 2) void k_gemm(const float* __restrict__ in,
                                                 const float* __restrict__ W,
                                                 const float* __restrict__ bias,
                                                 float* __restrict__ out) {
    extern __shared__ float sm[];
    unsigned long long* wp = (unsigned long long*)sm;  // [64][128] u64, 64KB
    float* xs = sm + 16384;                            // [64][128], 32KB
    int tid = threadIdx.x;
    int row0 = blockIdx.x * 64;

    // pack W: group g = (kp, l); cols 4l..4l+3 of k-rows 2kp, 2kp+1
    for (int g = tid; g < (C / 2) * 32; g += 256) {  // 2048 groups
        int kp = g >> 5;
        int l = g & 31;
        const float* wa = &W[(2 * kp) * C + 4 * l];
        const float* wb = &W[(2 * kp + 1) * C + 4 * l];
        float4 va = *(const float4*)wa;
        float4 vb = *(const float4*)wb;
        ulonglong2 pA, pB;
        pA.x = pk2(va.x, vb.x);   // col 4l
        pA.y = pk2(va.y, vb.y);   // col 4l+1
        pB.x = pk2(va.z, vb.z);   // col 4l+2
        pB.y = pk2(va.w, vb.w);   // col 4l+3
        *(ulonglong2*)&wp[kp * 128 + 2 * l] = pA;        // byte l*16 (conflict-free)
        *(ulonglong2*)&wp[kp * 128 + 64 + 2 * l] = pB;   // byte 512 + l*16
    }
    for (int i = tid; i < 64 * C / 4; i += 256) {
        int r = i >> 5;
        int gr = row0 + r;
        ((float4*)xs)[i] = (gr < NN) ? ((const float4*)in)[gr * 32 + (i & 31)]
                                     : make_float4(0.f, 0.f, 0.f, 0.f);
    }
    __syncthreads();

    int warp = tid >> 5, lane = tid & 31;
    int r0 = warp * 8;   // 8 warps x 8 rows
    int c0 = lane * 4;   // 32 lanes x 4 cols

    unsigned long long acc[8][4];
#pragma unroll
    for (int i = 0; i < 8; i++)
#pragma unroll
        for (int j = 0; j < 4; j++) acc[i][j] = 0ull;

#pragma unroll 2
    for (int kq = 0; kq < C / 4; kq++) {  // 4 k's per iteration
        int kp0 = 2 * kq;
        ulonglong2 w0A = *(ulonglong2*)&wp[kp0 * 128 + 2 * lane];
        ulonglong2 w0B = *(ulonglong2*)&wp[kp0 * 128 + 64 + 2 * lane];
        ulonglong2 w1A = *(ulonglong2*)&wp[(kp0 + 1) * 128 + 2 * lane];
        ulonglong2 w1B = *(ulonglong2*)&wp[(kp0 + 1) * 128 + 64 + 2 * lane];
#pragma unroll
        for (int i = 0; i < 8; i++) {
            ulonglong2 x4 = *(const ulonglong2*)&xs[(r0 + i) * C + 4 * kq];
            fma2(acc[i][0], x4.x, w0A.x);
            fma2(acc[i][1], x4.x, w0A.y);
            fma2(acc[i][2], x4.x, w0B.x);
            fma2(acc[i][3], x4.x, w0B.y);
            fma2(acc[i][0], x4.y, w1A.x);
            fma2(acc[i][1], x4.y, w1A.y);
            fma2(acc[i][2], x4.y, w1B.x);
            fma2(acc[i][3], x4.y, w1B.y);
        }
    }

    float4 bv = make_float4(0.f, 0.f, 0.f, 0.f);
    if (bias) bv = ((const float4*)bias)[lane];
#pragma unroll
    for (int i = 0; i < 8; i++) {
        int gr = row0 + r0 + i;
        if (gr < NN) {
            float2 p0 = unpk2(acc[i][0]);
            float2 p1 = unpk2(acc[i][1]);
            float2 p2 = unpk2(acc[i][2]);
            float2 p3 = unpk2(acc[i][3]);
            *(float4*)&out[gr * C + c0] =
                make_float4(p0.x + p0.y + bv.x, p1.x + p1.y + bv.y,
                            p2.x + p2.y + bv.z, p3.x + p3.y + bv.w);
        }
    }
}

// ---------------- CSR gather: one warp per node, edge loop unrolled x4 ----------------
__global__ __launch_bounds__(256) void k_gather(const float* __restrict__ t,
                                                const float* __restrict__ b,
                                                const float* __restrict__ a,
                                                float* __restrict__ skip_io,
                                                float* __restrict__ out, int mode) {
    int node = (blockIdx.x * 256 + threadIdx.x) >> 5;
    int lane = threadIdx.x & 31;
    if (node >= NN) return;

    float di = g_dis[node];
    float d2 = di * di;
    float4 bv = ((const float4*)b)[lane];
    float4 tv = ((const float4*)t)[node * 32 + lane];
    float4 acc = make_float4(bv.x + tv.x * d2, bv.y + tv.y * d2,
                             bv.z + tv.z * d2, bv.w + tv.w * d2);

    int beg = g_off[node], end = g_off[node + 1];
    for (int base = beg; base < end; base += 32) {
        int idx = base + lane;
        int s = 0;
        float w = 0.f;
        if (idx < end) {
            s = g_csrc[idx];
            w = g_dis[s] * di;
        }
        int cnt = min(32, end - base);
        int j = 0;
        for (; j + 4 <= cnt; j += 4) {
            int s0 = __shfl_sync(0xffffffffu, s, j);
            int s1 = __shfl_sync(0xffffffffu, s, j + 1);
            int s2 = __shfl_sync(0xffffffffu, s, j + 2);
            int s3 = __shfl_sync(0xffffffffu, s, j + 3);
            float w0 = __shfl_sync(0xffffffffu, w, j);
            float w1 = __shfl_sync(0xffffffffu, w, j + 1);
            float w2 = __shfl_sync(0xffffffffu, w, j + 2);
            float w3 = __shfl_sync(0xffffffffu, w, j + 3);
            float4 v0 = ((const float4*)t)[s0 * 32 + lane];
            float4 v1 = ((const float4*)t)[s1 * 32 + lane];
            float4 v2 = ((const float4*)t)[s2 * 32 + lane];
            float4 v3 = ((const float4*)t)[s3 * 32 + lane];
            acc.x += v0.x * w0; acc.y += v0.y * w0; acc.z += v0.z * w0; acc.w += v0.w * w0;
            acc.x += v1.x * w1; acc.y += v1.y * w1; acc.z += v1.z * w1; acc.w += v1.w * w1;
            acc.x += v2.x * w2; acc.y += v2.y * w2; acc.z += v2.z * w2; acc.w += v2.w * w2;
            acc.x += v3.x * w3; acc.y += v3.y * w3; acc.z += v3.z * w3; acc.w += v3.w * w3;
        }
        for (; j < cnt; j++) {
            int sj = __shfl_sync(0xffffffffu, s, j);
            float wj = __shfl_sync(0xffffffffu, w, j);
            float4 v = ((const float4*)t)[sj * 32 + lane];
            acc.x += v.x * wj; acc.y += v.y * wj; acc.z += v.z * wj; acc.w += v.w * wj;
        }
    }

    float4 av = ((const float4*)a)[lane];
    float4 p;
    p.x = acc.x >= 0.f ? acc.x : av.x * acc.x;
    p.y = acc.y >= 0.f ? acc.y : av.y * acc.y;
    p.z = acc.z >= 0.f ? acc.z : av.z * acc.z;
    p.w = acc.w >= 0.f ? acc.w : av.w * acc.w;

    if (mode == 0) {
        float4 sk = ((const float4*)skip_io)[node * 32 + lane];
        ((float4*)skip_io)[node * 32 + lane] =
            make_float4(sk.x + p.x, sk.y + p.y, sk.z + p.z, sk.w + p.w);
    } else {
        ((float4*)out)[node * 32 + lane] = p;
    }
}

extern "C" void kernel_launch(void* const* d_in, const int* in_sizes, int n_in,
                              void* d_out, int out_size) {
    const float* x  = (const float*)d_in[0];
    const int*   ei = (const int*)d_in[1];
    const float* W0 = (const float*)d_in[2];
    const float* b0 = (const float*)d_in[3];
    const float* W1 = (const float*)d_in[4];
    const float* b1 = (const float*)d_in[5];
    const float* Ws = (const float*)d_in[6];
    const float* bs = (const float*)d_in[7];
    const float* a  = (const float*)d_in[8];
    float* out = (float*)d_out;

    const int4* src4 = (const int4*)ei;
    const int4* dst4 = (const int4*)(ei + NE);

    float *t, *skip;
    cudaGetSymbolAddress((void**)&t, g_t);
    cudaGetSymbolAddress((void**)&skip, g_skip);

    const int GEMM_SMEM = (C * C + 64 * C) * 4;  // 96KB
    cudaFuncSetAttribute(k_gemm, cudaFuncAttributeMaxDynamicSharedMemorySize,
                         GEMM_SMEM);

    const int GEMM_GRID = (NN + 63) / 64;
    const int GATHER_GRID = (NN * 32 + 255) / 256;
    const int E4 = NE / 4;

    // 9 launches; index 3 (ncu capture slot) = first k_gemm
    k_deg_count<<<(E4 + 255) / 256, 256>>>(dst4);                 // 0
    k_scan_a<<<NB, 256>>>();                                      // 1
    k_scan_c<<<NB, 256>>>();                                      // 2

    k_gemm<<<GEMM_GRID, 256, GEMM_SMEM>>>(x, Ws, bs, skip);       // 3: skip = x@Ws+bs  [ncu]
    k_gemm<<<GEMM_GRID, 256, GEMM_SMEM>>>(x, W0, nullptr, t);     // 4: t = x@W0

    k_bucket<<<(E4 + 255) / 256, 256>>>(src4, dst4);              // 5 (also re-zeros g_cnt)
    k_gather<<<GATHER_GRID, 256>>>(t, b0, a, skip, nullptr, 0);   // 6: skip = u

    k_gemm<<<GEMM_GRID, 256, GEMM_SMEM>>>(skip, W1, nullptr, t);  // 7: t = u@W1
    k_gather<<<GATHER_GRID, 256>>>(t, b1, a, nullptr, out, 1);    // 8: out
}